// round 13
// baseline (speedup 1.0000x reference)
#include <cuda_runtime.h>
#include <cuda_fp16.h>
#include <cstdint>

// ---------------------------------------------------------------------------
// out = sum_p w_p * kron8(blocks[idx[p]])  -> 256x256
// G[a,b] = sum_p (w_p A_p[a]) B_p[b];  out[(iH16+iL),(jH16+jL)] = G[iH16+jH, iL16+jL]
// A = w*ternary -> split w = w_hi + w_lo (fp16): A_hi, A_lo, B exact fp16.
// R13: grid (4,4,8) = 128 CTAs, 64x64 tiles, each CTA accumulates 2 sub-chunks
//      of 256 genomes in registers -> SPLITK=8, partials 2.1 MB (was 4.2).
// ---------------------------------------------------------------------------

#define POP      4096
#define SPLITK   8
#define KCHUNK   512                 // per CTA (2 sub-chunks of 256)
#define SUBK     256
#define LDTA     72                  // A tile row stride (halfs), 64 + pad
#define LDTB     72                  // B tile row stride (halfs), 64 + pad

__device__ float g_part[SPLITK * 256 * 256];   // 2.1 MB split-K partials

// ---------------- warp-MMA helpers (sm_80+ PTX, valid at compute_103) ------
__device__ __forceinline__ unsigned smem_u32(const void* p) {
    unsigned a;
    asm("{ .reg .u64 t; cvta.to.shared.u64 t, %1; cvt.u32.u64 %0, t; }" : "=r"(a) : "l"(p));
    return a;
}
__device__ __forceinline__ void ldsm_x4_t(uint32_t* r, unsigned a) {
    asm volatile("ldmatrix.sync.aligned.m8n8.x4.trans.shared.b16 {%0,%1,%2,%3}, [%4];"
                 : "=r"(r[0]), "=r"(r[1]), "=r"(r[2]), "=r"(r[3]) : "r"(a));
}
__device__ __forceinline__ void ldsm_x2_t(uint32_t* r, unsigned a) {
    asm volatile("ldmatrix.sync.aligned.m8n8.x2.trans.shared.b16 {%0,%1}, [%2];"
                 : "=r"(r[0]), "=r"(r[1]) : "r"(a));
}
__device__ __forceinline__ void mma16816(float* d, const uint32_t* a, const uint32_t* b) {
    asm volatile("mma.sync.aligned.m16n8k16.row.col.f32.f16.f16.f32 "
                 "{%0,%1,%2,%3}, {%4,%5,%6,%7}, {%8,%9}, {%0,%1,%2,%3};"
                 : "+f"(d[0]), "+f"(d[1]), "+f"(d[2]), "+f"(d[3])
                 : "r"(a[0]), "r"(a[1]), "r"(a[2]), "r"(a[3]), "r"(b[0]), "r"(b[1]));
}

// ---------------------------------------------------------------------------
// Fused kernel: grid (4 mb, 4 nb, 8 z) = 128 CTAs, 512 threads (16 warps).
// A tile 64 a-cols (a bits [7:6] = mb), B tile 64 b-cols (b bits [7:6] = nb).
// Warp-tile 16x16: wm = wid&3, wn = wid>>2.
// ---------------------------------------------------------------------------
__global__ void __launch_bounds__(512, 1) fused_kernel(
        const float* __restrict__ w,
        const int*   __restrict__ idxg,
        const float* __restrict__ bbg) {
    extern __shared__ __half smem[];
    __half* As = smem;                               // [SUBK][LDTA]
    __half* Al = smem + SUBK * LDTA;
    __half* Bs = smem + 2 * SUBK * LDTA;             // [SUBK][LDTB]
    __shared__ float bb[144];
    __shared__ int   sidx[KCHUNK * 8];               // 16 KB
    __shared__ float sw[KCHUNK];
    __shared__ uint4 vt[4 * KCHUNK];                 // 32 KB: 2 uint4/entry

    const int tid = threadIdx.x, lane = tid & 31, wid = tid >> 5;
    const int mb = blockIdx.x, nb = blockIdx.y, z = blockIdx.z;
    const int gbase = z * KCHUNK;

    // ---- Stage constants for both sub-chunks (no guards: 8*512 = 4096) ----
    if (tid < 144) bb[tid] = bbg[tid];
    #pragma unroll
    for (int i = tid; i < KCHUNK * 8; i += 512)
        sidx[i] = __ldg(&idxg[gbase * 8 + i]);
    if (tid < KCHUNK) sw[tid] = __ldg(&w[gbase + tid]);
    __syncthreads();

    // ---- V-tables for both sides, all 512 genomes (1024 tasks) ----
    #pragma unroll
    for (int i = tid; i < 2 * KCHUNK; i += 512) {
        const int gl = i & (KCHUNK - 1);
        const int cb = (i < KCHUNK) ? 2 : 6;
        const int ia = sidx[gl * 8 + cb], ib = sidx[gl * 8 + cb + 1];
        __half2 Vh[8];
        #pragma unroll
        for (int p = 0; p < 2; p++)
          #pragma unroll
          for (int q = 0; q < 2; q++)
            #pragma unroll
            for (int r = 0; r < 2; r++) {
                const float va = bb[ia * 4 + p * 2 + r];
                Vh[((p*2+q)*4 + r*2) >> 1] =
                    __floats2half2_rn(va * bb[ib * 4 + q * 2],
                                      va * bb[ib * 4 + q * 2 + 1]);
            }
        uint4 u0, u1;
        u0.x = *(unsigned*)&Vh[0]; u0.y = *(unsigned*)&Vh[1];
        u0.z = *(unsigned*)&Vh[2]; u0.w = *(unsigned*)&Vh[3];
        u1.x = *(unsigned*)&Vh[4]; u1.y = *(unsigned*)&Vh[5];
        u1.z = *(unsigned*)&Vh[6]; u1.w = *(unsigned*)&Vh[7];
        vt[i * 2]     = u0;
        vt[i * 2 + 1] = u1;
    }

    // ---- MMA lane constants ----
    const int wm = wid & 3;
    const int wn = wid >> 2;
    const int arow = (lane & 7) + ((lane >> 4) << 3);
    const int acol = wm * 16 + ((lane >> 3) & 1) * 8;
    const int bl = lane & 15;
    const int brow = (bl & 7) + ((bl >> 3) << 3);
    const unsigned aHi = smem_u32(&As[arow * LDTA + acol]);
    const unsigned aLo = smem_u32(&Al[arow * LDTA + acol]);
    const unsigned bBa = smem_u32(&Bs[brow * LDTB + wn * 16]);

    float acc[2][4];
    #pragma unroll
    for (int j = 0; j < 2; j++)
        #pragma unroll
        for (int q = 0; q < 4; q++) acc[j][q] = 0.f;

    // ==== two sub-chunks, register accumulation ====
    for (int c = 0; c < 2; c++) {
        __syncthreads();                 // vt ready (c=0) / prev MMA done (c=1)

        // ---- Build A hi/lo: 1024 tasks (row, xi), x = mb*4 + xi ----
        #pragma unroll
        for (int i = tid; i < SUBK * 4; i += 512) {
            const int row = i >> 2, xi = i & 3;
            const int gl = c * SUBK + row;
            const float u = bb[sidx[gl*8+0] * 4 + (mb >> 1) * 2 + (xi >> 1)]
                          * bb[sidx[gl*8+1] * 4 + (mb & 1) * 2 + (xi & 1)];
            const float wf  = sw[gl];
            const float whf = __half2float(__float2half_rn(wf));
            const float wlf = __half2float(__float2half_rn(wf - whf));
            const __half2 ph = __float2half2_rn(whf * u);   // exact {0, +/-w_hi}
            const __half2 pl = __float2half2_rn(wlf * u);

            const uint4 v0 = vt[gl * 2], v1 = vt[gl * 2 + 1];
            const unsigned vv[8] = {v0.x, v0.y, v0.z, v0.w, v1.x, v1.y, v1.z, v1.w};
            #pragma unroll
            for (int qq = 0; qq < 4; qq++) {
                const __half2 a0 = *(const __half2*)&vv[2*qq];
                const __half2 a1 = *(const __half2*)&vv[2*qq+1];
                __half2 h0 = __hmul2(ph, a0), h1 = __hmul2(ph, a1);
                __half2 l0 = __hmul2(pl, a0), l1 = __hmul2(pl, a1);
                const int col = (qq << 4) | (xi << 2);
                uint2 uh; uh.x = *(unsigned*)&h0; uh.y = *(unsigned*)&h1;
                uint2 ul; ul.x = *(unsigned*)&l0; ul.y = *(unsigned*)&l1;
                *(uint2*)&As[row * LDTA + col] = uh;
                *(uint2*)&Al[row * LDTA + col] = ul;
            }
        }

        // ---- Build B: 1024 tasks (row, xi), x = nb*4 + xi ----
        #pragma unroll
        for (int i = tid; i < SUBK * 4; i += 512) {
            const int row = i >> 2, xi = i & 3;
            const int gl = c * SUBK + row;
            const float u = bb[sidx[gl*8+4] * 4 + (nb >> 1) * 2 + (xi >> 1)]
                          * bb[sidx[gl*8+5] * 4 + (nb & 1) * 2 + (xi & 1)];
            const __half2 uh2 = __float2half2_rn(u);

            const uint4 v0 = vt[(KCHUNK + gl) * 2], v1 = vt[(KCHUNK + gl) * 2 + 1];
            const unsigned vv[8] = {v0.x, v0.y, v0.z, v0.w, v1.x, v1.y, v1.z, v1.w};
            #pragma unroll
            for (int qq = 0; qq < 4; qq++) {
                const __half2 a0 = *(const __half2*)&vv[2*qq];
                const __half2 a1 = *(const __half2*)&vv[2*qq+1];
                __half2 h0 = __hmul2(uh2, a0), h1 = __hmul2(uh2, a1);
                const int col = (qq << 4) | (xi << 2);
                uint2 uv; uv.x = *(unsigned*)&h0; uv.y = *(unsigned*)&h1;
                *(uint2*)&Bs[row * LDTB + col] = uv;
            }
        }
        __syncthreads();

        // ---- HMMA: 16 k-steps, warp-tile 16x16 ----
        #pragma unroll
        for (int ks = 0; ks < SUBK / 16; ks++) {
            const unsigned ko = (unsigned)(ks * 16 * LDTA * 2);  // LDTA==LDTB
            uint32_t bf[2][2];
            ldsm_x2_t(bf[0], bBa + ko);
            ldsm_x2_t(bf[1], bBa + ko + 16);
            uint32_t ah[4], al[4];
            ldsm_x4_t(ah, aHi + ko);
            ldsm_x4_t(al, aLo + ko);
            #pragma unroll
            for (int nt = 0; nt < 2; nt++) {
                mma16816(acc[nt], ah, bf[nt]);
                mma16816(acc[nt], al, bf[nt]);
            }
        }
    }

    // ---- Epilogue: 16x16 per warp into 64x64 split-K partial ----
    float* part = g_part + z * 65536;
    const int r0 = mb * 64 + wm * 16;
    const int c0 = nb * 64 + wn * 16;
    #pragma unroll
    for (int nt = 0; nt < 2; nt++) {
        const int a = r0 + (lane >> 2);
        const int b = c0 + nt * 8 + (lane & 3) * 2;
        *(float2*)&part[a * 256 + b]       = make_float2(acc[nt][0], acc[nt][1]);
        *(float2*)&part[(a + 8) * 256 + b] = make_float2(acc[nt][2], acc[nt][3]);
    }
}

// ---------------------------------------------------------------------------
// Reduce: 2 threads per output float4, 4 slices each (MLP=4), shfl combine,
// Kronecker-permuted store. grid 128 x 256 thr = 32K threads, 2.1 MB read.
// ---------------------------------------------------------------------------
__global__ void __launch_bounds__(256) reduce_kernel(float* __restrict__ out) {
    const int t = threadIdx.x;
    const int o = blockIdx.x * 128 + (t >> 1);       // output float4 index
    const int h = t & 1;                             // k-half
    const float4* src = (const float4*)g_part + o;

    float4 v[4];
    #pragma unroll
    for (int k = 0; k < 4; k++) v[k] = src[(size_t)(h * 4 + k) * 16384];

    float4 s = v[0];
    #pragma unroll
    for (int k = 1; k < 4; k++) {
        s.x += v[k].x; s.y += v[k].y; s.z += v[k].z; s.w += v[k].w;
    }
    s.x += __shfl_xor_sync(0xffffffffu, s.x, 1);
    s.y += __shfl_xor_sync(0xffffffffu, s.y, 1);
    s.z += __shfl_xor_sync(0xffffffffu, s.z, 1);
    s.w += __shfl_xor_sync(0xffffffffu, s.w, 1);

    if (h == 0) {
        const int tt = o * 4;
        const int a = tt >> 8, b = tt & 255;
        const int iH = a >> 4, jH = a & 15;
        const int iL = b >> 4, jL = b & 15;          // jL multiple of 4
        *(float4*)(out + (iH * 16 + iL) * 256 + jH * 16 + jL) = s;
    }
}

extern "C" void kernel_launch(void* const* d_in, const int* in_sizes, int n_in,
                              void* d_out, int out_size) {
    const float* w   = (const float*)d_in[0];
    const int*   idx = (const int*)  d_in[1];
    const float* bb  = (const float*)d_in[2];

    const int smem_bytes = 3 * SUBK * LDTA * (int)sizeof(__half);  // 110592
    cudaFuncSetAttribute(fused_kernel, cudaFuncAttributeMaxDynamicSharedMemorySize, smem_bytes);

    fused_kernel<<<dim3(4, 4, SPLITK), 512, smem_bytes>>>(w, idx, bb);
    reduce_kernel<<<128, 256>>>((float*)d_out);
}

// round 14
// speedup vs baseline: 1.1572x; 1.1572x over previous
#include <cuda_runtime.h>
#include <cuda_fp16.h>
#include <cstdint>

// ---------------------------------------------------------------------------
// out = sum_p w_p * kron8(blocks[idx[p]])  -> 256x256
// G[a,b] = sum_p (w_p A_p[a]) B_p[b];  out[(iH16+iL),(jH16+jL)] = G[iH16+jH, iL16+jL]
// A = w*ternary -> split w = w_hi + w_lo (fp16): A_hi, A_lo, B exact fp16.
// G = A_hi^T B + A_lo^T B via mma.sync f16->f32, tiles generated in smem.
// R14: fused kernel = R12 verbatim (7.6us). Reduce launched via PDL
//      (programmatic stream serialization) to hide its launch latency;
//      1 thread/output, 16 loads in flight (MLP=16).
// ---------------------------------------------------------------------------

#define POP      4096
#define SPLITK   16
#define KCHUNK   256                 // 16*256 = 4096 exactly
#define KSTEPS   16                  // 256/16
#define LDTA     72                  // A tile row stride (halfs), 64 + pad
#define LDTB     136                 // B tile row stride (halfs), 128 + pad

__device__ float g_part[SPLITK * 256 * 256];   // 4.2 MB split-K partials

// ---------------- warp-MMA helpers (sm_80+ PTX, valid at compute_103) ------
__device__ __forceinline__ unsigned smem_u32(const void* p) {
    unsigned a;
    asm("{ .reg .u64 t; cvta.to.shared.u64 t, %1; cvt.u32.u64 %0, t; }" : "=r"(a) : "l"(p));
    return a;
}
__device__ __forceinline__ void ldsm_x4_t(uint32_t* r, unsigned a) {
    asm volatile("ldmatrix.sync.aligned.m8n8.x4.trans.shared.b16 {%0,%1,%2,%3}, [%4];"
                 : "=r"(r[0]), "=r"(r[1]), "=r"(r[2]), "=r"(r[3]) : "r"(a));
}
__device__ __forceinline__ void ldsm_x2_t(uint32_t* r, unsigned a) {
    asm volatile("ldmatrix.sync.aligned.m8n8.x2.trans.shared.b16 {%0,%1}, [%2];"
                 : "=r"(r[0]), "=r"(r[1]) : "r"(a));
}
__device__ __forceinline__ void mma16816(float* d, const uint32_t* a, const uint32_t* b) {
    asm volatile("mma.sync.aligned.m16n8k16.row.col.f32.f16.f16.f32 "
                 "{%0,%1,%2,%3}, {%4,%5,%6,%7}, {%8,%9}, {%0,%1,%2,%3};"
                 : "+f"(d[0]), "+f"(d[1]), "+f"(d[2]), "+f"(d[3])
                 : "r"(a[0]), "r"(a[1]), "r"(a[2]), "r"(a[3]), "r"(b[0]), "r"(b[1]));
}

// ---------------------------------------------------------------------------
// Fused kernel (R12 verbatim): grid (4 mb, 2 nb, 16 z) = 128 CTAs, 512 thr.
// ---------------------------------------------------------------------------
__global__ void __launch_bounds__(512, 1) fused_kernel(
        const float* __restrict__ w,
        const int*   __restrict__ idxg,
        const float* __restrict__ bbg) {
    extern __shared__ __half smem[];
    __half* As = smem;                               // [KCHUNK][LDTA]
    __half* Al = smem + KCHUNK * LDTA;
    __half* Bs = smem + 2 * KCHUNK * LDTA;           // [KCHUNK][LDTB]
    __shared__ float bb[144];
    __shared__ int   sidx[KCHUNK * 8];
    __shared__ float sw[KCHUNK];
    __shared__ uint4 vt[4 * KCHUNK];                 // V-tables: 2 uint4/entry

    const int tid = threadIdx.x, lane = tid & 31, wid = tid >> 5;
    const int mb = blockIdx.x, nb = blockIdx.y, z = blockIdx.z;
    const int gbase = z * KCHUNK;

    if (tid < 144) bb[tid] = bbg[tid];
    #pragma unroll
    for (int i = tid; i < KCHUNK * 8; i += 512)
        sidx[i] = __ldg(&idxg[gbase * 8 + i]);
    if (tid < KCHUNK) sw[tid] = __ldg(&w[gbase + tid]);
    __syncthreads();

    {
        const int i = tid;                   // 512 tasks, one per thread
        const int gl = i & (KCHUNK - 1);
        const int cb = (i < KCHUNK) ? 2 : 6;
        const int ia = sidx[gl * 8 + cb], ib = sidx[gl * 8 + cb + 1];
        __half2 Vh[8];
        #pragma unroll
        for (int p = 0; p < 2; p++)
          #pragma unroll
          for (int q = 0; q < 2; q++)
            #pragma unroll
            for (int r = 0; r < 2; r++) {
                const float va = bb[ia * 4 + p * 2 + r];
                Vh[((p*2+q)*4 + r*2) >> 1] =
                    __floats2half2_rn(va * bb[ib * 4 + q * 2],
                                      va * bb[ib * 4 + q * 2 + 1]);
            }
        uint4 u0, u1;
        u0.x = *(unsigned*)&Vh[0]; u0.y = *(unsigned*)&Vh[1];
        u0.z = *(unsigned*)&Vh[2]; u0.w = *(unsigned*)&Vh[3];
        u1.x = *(unsigned*)&Vh[4]; u1.y = *(unsigned*)&Vh[5];
        u1.z = *(unsigned*)&Vh[6]; u1.w = *(unsigned*)&Vh[7];
        vt[i * 2]     = u0;
        vt[i * 2 + 1] = u1;
    }
    __syncthreads();

    #pragma unroll
    for (int i = tid; i < KCHUNK * 4; i += 512) {
        const int gl = i >> 2, xi = i & 3;
        const float u = bb[sidx[gl*8+0] * 4 + (mb >> 1) * 2 + (xi >> 1)]
                      * bb[sidx[gl*8+1] * 4 + (mb & 1) * 2 + (xi & 1)];
        const float wf  = sw[gl];
        const float whf = __half2float(__float2half_rn(wf));
        const float wlf = __half2float(__float2half_rn(wf - whf));
        const __half2 ph = __float2half2_rn(whf * u);   // exact {0, +/-w_hi}
        const __half2 pl = __float2half2_rn(wlf * u);

        const uint4 v0 = vt[gl * 2], v1 = vt[gl * 2 + 1];
        const unsigned vv[8] = {v0.x, v0.y, v0.z, v0.w, v1.x, v1.y, v1.z, v1.w};
        #pragma unroll
        for (int qq = 0; qq < 4; qq++) {
            const __half2 a0 = *(const __half2*)&vv[2*qq];
            const __half2 a1 = *(const __half2*)&vv[2*qq+1];
            __half2 h0 = __hmul2(ph, a0), h1 = __hmul2(ph, a1);
            __half2 l0 = __hmul2(pl, a0), l1 = __hmul2(pl, a1);
            const int col = (qq << 4) | (xi << 2);
            uint2 uh; uh.x = *(unsigned*)&h0; uh.y = *(unsigned*)&h1;
            uint2 ul; ul.x = *(unsigned*)&l0; ul.y = *(unsigned*)&l1;
            *(uint2*)&As[gl * LDTA + col] = uh;
            *(uint2*)&Al[gl * LDTA + col] = ul;
        }
    }

    #pragma unroll
    for (int i = tid; i < KCHUNK * 8; i += 512) {
        const int gl = i >> 3, xi = i & 7;
        const float u = bb[sidx[gl*8+4] * 4 + nb * 2 + ((xi >> 1) & 1)]
                      * bb[sidx[gl*8+5] * 4 + ((xi >> 2) & 1) * 2 + (xi & 1)];
        const __half2 uh2 = __float2half2_rn(u);

        const uint4 v0 = vt[(KCHUNK + gl) * 2], v1 = vt[(KCHUNK + gl) * 2 + 1];
        const unsigned vv[8] = {v0.x, v0.y, v0.z, v0.w, v1.x, v1.y, v1.z, v1.w};
        const int colbase = (((xi >> 2) & 1) << 6) | ((xi & 3) << 2);
        #pragma unroll
        for (int qq = 0; qq < 4; qq++) {
            const __half2 a0 = *(const __half2*)&vv[2*qq];
            const __half2 a1 = *(const __half2*)&vv[2*qq+1];
            __half2 h0 = __hmul2(uh2, a0), h1 = __hmul2(uh2, a1);
            const int col = colbase | (qq << 4);
            uint2 uv; uv.x = *(unsigned*)&h0; uv.y = *(unsigned*)&h1;
            *(uint2*)&Bs[gl * LDTB + col] = uv;
        }
    }
    __syncthreads();

    const int wm = wid & 3;
    const int wn = wid >> 2;
    const int arow = (lane & 7) + ((lane >> 4) << 3);
    const int acol = wm * 16 + ((lane >> 3) & 1) * 8;
    const int bl = lane & 15;
    const int brow = (bl & 7) + ((bl >> 3) << 3);

    const unsigned aHi = smem_u32(&As[arow * LDTA + acol]);
    const unsigned aLo = smem_u32(&Al[arow * LDTA + acol]);
    const unsigned bBa = smem_u32(&Bs[brow * LDTB + wn * 32]);

    float acc[4][4];
    #pragma unroll
    for (int j = 0; j < 4; j++)
        #pragma unroll
        for (int q = 0; q < 4; q++) acc[j][q] = 0.f;

    #pragma unroll
    for (int ks = 0; ks < KSTEPS; ks++) {
        const unsigned koa = (unsigned)(ks * 16 * LDTA * 2);
        const unsigned kob = (unsigned)(ks * 16 * LDTB * 2);
        uint32_t bf[4][2];
        #pragma unroll
        for (int nt = 0; nt < 4; nt++) ldsm_x2_t(bf[nt], bBa + kob + nt * 16);
        uint32_t ah[4], al[4];
        ldsm_x4_t(ah, aHi + koa);
        ldsm_x4_t(al, aLo + koa);
        #pragma unroll
        for (int nt = 0; nt < 4; nt++) {
            mma16816(acc[nt], ah, bf[nt]);
            mma16816(acc[nt], al, bf[nt]);
        }
    }

    float* part = g_part + z * 65536;
    const int r0 = mb * 64 + wm * 16;
    const int c0 = nb * 128 + wn * 32;
    #pragma unroll
    for (int nt = 0; nt < 4; nt++) {
        const int a = r0 + (lane >> 2);
        const int b = c0 + nt * 8 + (lane & 3) * 2;
        *(float2*)&part[a * 256 + b]       = make_float2(acc[nt][0], acc[nt][1]);
        *(float2*)&part[(a + 8) * 256 + b] = make_float2(acc[nt][2], acc[nt][3]);
    }
}

// ---------------------------------------------------------------------------
// Reduce (PDL secondary): 1 thread per output float4, all 16 slice-loads in
// flight (MLP=16). cudaGridDependencySynchronize() gates on fused's memory.
// grid 64 x 256 thr = 16K threads.
// ---------------------------------------------------------------------------
__global__ void __launch_bounds__(256) reduce_kernel(float* __restrict__ out) {
    cudaGridDependencySynchronize();                 // wait for fused writes

    const int o = blockIdx.x * 256 + threadIdx.x;    // output float4 index
    const float4* src = (const float4*)g_part + o;

    float4 v[16];
    #pragma unroll
    for (int k = 0; k < 16; k++) v[k] = src[(size_t)k * 16384];

    float4 s = v[0];
    #pragma unroll
    for (int k = 1; k < 16; k++) {
        s.x += v[k].x; s.y += v[k].y; s.z += v[k].z; s.w += v[k].w;
    }
    const int tt = o * 4;
    const int a = tt >> 8, b = tt & 255;
    const int iH = a >> 4, jH = a & 15;
    const int iL = b >> 4, jL = b & 15;              // jL multiple of 4
    *(float4*)(out + (iH * 16 + iL) * 256 + jH * 16 + jL) = s;
}

extern "C" void kernel_launch(void* const* d_in, const int* in_sizes, int n_in,
                              void* d_out, int out_size) {
    const float* w   = (const float*)d_in[0];
    const int*   idx = (const int*)  d_in[1];
    const float* bb  = (const float*)d_in[2];

    const int smem_bytes = (2 * KCHUNK * LDTA + KCHUNK * LDTB) * (int)sizeof(__half); // 143360
    cudaFuncSetAttribute(fused_kernel, cudaFuncAttributeMaxDynamicSharedMemorySize, smem_bytes);

    fused_kernel<<<dim3(4, 2, SPLITK), 512, smem_bytes>>>(w, idx, bb);

    // PDL launch of the reduce: overlaps its launch latency with fused_kernel;
    // cudaGridDependencySynchronize() inside enforces the data dependency.
    cudaLaunchAttribute attrs[1];
    attrs[0].id = cudaLaunchAttributeProgrammaticStreamSerialization;
    attrs[0].val.programmaticStreamSerializationAllowed = 1;
    cudaLaunchConfig_t cfg = {};
    cfg.gridDim = dim3(64, 1, 1);
    cfg.blockDim = dim3(256, 1, 1);
    cfg.dynamicSmemBytes = 0;
    cfg.stream = 0;
    cfg.attrs = attrs;
    cfg.numAttrs = 1;
    cudaLaunchKernelEx(&cfg, reduce_kernel, (float*)d_out);
}